// round 5
// baseline (speedup 1.0000x reference)
#include <cuda_runtime.h>

#define NG 1024
#define NN 40
#define M_EDGES 780
#define NODES (NG*NN)          /* 40960 */
#define H_ELEMS (NODES*64)     /* 2621440 */
#define X_PER_G (160*160)      /* 25600 */
#define X_ELEMS ((size_t)NG*X_PER_G)

// scratch: u = hg @ We0 per node (10.5 MB, fits in L2)
__device__ float g_u[NODES * 64];
// fallback scratch if the harness's d_out does not cover h and/or X
__device__ float g_h[H_ELEMS];
__device__ float g_x[NG * X_PER_G];

__constant__ int c_smat[16] = {0,1,2,3, 1,4,5,6, 2,5,7,8, 3,6,8,9};

__device__ __forceinline__ float lrelu(float v){ return v > 0.f ? v : 0.1f*v; }

// packed fp32x2 FMA (sm_10x): 2 MACs per instruction
__device__ __forceinline__ unsigned long long ffma2(unsigned long long a, unsigned long long b, unsigned long long c){
    unsigned long long d;
    asm("fma.rn.f32x2 %0, %1, %2, %3;" : "=l"(d) : "l"(a), "l"(b), "l"(c));
    return d;
}
__device__ __forceinline__ unsigned long long splat2(float x){
    unsigned long long r;
    asm("mov.b64 %0, {%1, %1};" : "=l"(r) : "f"(x));
    return r;
}
__device__ __forceinline__ float f2lo(unsigned long long a){ return __uint_as_float((unsigned)(a & 0xffffffffULL)); }
__device__ __forceinline__ float f2hi(unsigned long long a){ return __uint_as_float((unsigned)(a >> 32)); }

// ---------------------------------------------------------------------------
// K1: GCN — complete graph => gcn(h)[j] = (colsum(t) - t[j])/39 + b, t = h@W
// ---------------------------------------------------------------------------
__global__ __launch_bounds__(128) void gcn_kernel(
    const float* __restrict__ x,
    const float* __restrict__ Wg0, const float* __restrict__ bg0,
    const float* __restrict__ Wg1, const float* __restrict__ bg1,
    const float* __restrict__ Wg2, const float* __restrict__ bg2,
    float* __restrict__ hout)
{
    __shared__ float sh[NN*64];
    __shared__ float st[NN*64];
    __shared__ float sw[32*64];
    __shared__ float ssum[64];
    const int g = blockIdx.x, tid = threadIdx.x;

    for (int idx = tid; idx < NN*6; idx += 128){
        int n = idx/6, c = idx - n*6;
        sh[n*64+c] = x[(g*NN+n)*16 + c];
    }
    __syncthreads();

    auto layer = [&](int ind, int outd, const float* W, const float* b, bool act){
        for (int idx = tid; idx < ind*outd; idx += 128) sw[idx] = W[idx];
        __syncthreads();
        for (int idx = tid; idx < NN*outd; idx += 128){
            int n = idx/outd, o = idx - n*outd;
            float a = 0.f;
            for (int k = 0; k < ind; k++) a += sh[n*64+k]*sw[k*outd+o];
            st[n*64+o] = a;
        }
        __syncthreads();
        for (int o = tid; o < outd; o += 128){
            float s = 0.f;
            for (int n = 0; n < NN; n++) s += st[n*64+o];
            ssum[o] = s;
        }
        __syncthreads();
        const float inv = 1.f/39.f;
        for (int idx = tid; idx < NN*outd; idx += 128){
            int n = idx/outd, o = idx - n*outd;
            float v = (ssum[o] - st[n*64+o])*inv + b[o];
            if (act) v = lrelu(v);
            sh[n*64+o] = v;
        }
        __syncthreads();
    };
    layer(6, 32, Wg0, bg0, true);
    layer(32, 32, Wg1, bg1, true);
    layer(32, 64, Wg2, bg2, false);

    float* hrow = hout + (size_t)g*NN*64;
    for (int idx = tid; idx < NN*64; idx += 128) hrow[idx] = sh[idx];
}

// ---------------------------------------------------------------------------
// 128x64x64 GEMM tile, 256 threads, thread tile = 4 rows x 8 outs, FFMA2.
// Zin: [k][e] stride 128. Wsp: splatted weights [k][o]{w,w} stride 128.
// Zout: [o][e] stride 128.
// ---------------------------------------------------------------------------
template<bool ACT, bool HASB>
__device__ __forceinline__ void gemm128(const float* Zin, float* Zout,
                                        const float* Wsp, const float* bias,
                                        int eg, int og)
{
    unsigned long long acc[16];
#pragma unroll
    for (int i = 0; i < 16; i++) acc[i] = 0ULL;

#pragma unroll 4
    for (int k = 0; k < 64; k++){
        ulonglong2 z = *reinterpret_cast<const ulonglong2*>(Zin + k*128 + eg*4);
        const ulonglong2* wp = reinterpret_cast<const ulonglong2*>(Wsp + k*128 + og*16);
        ulonglong2 w0 = wp[0], w1 = wp[1], w2 = wp[2], w3 = wp[3];
        acc[0] = ffma2(z.x, w0.x, acc[0]);  acc[1]  = ffma2(z.y, w0.x, acc[1]);
        acc[2] = ffma2(z.x, w0.y, acc[2]);  acc[3]  = ffma2(z.y, w0.y, acc[3]);
        acc[4] = ffma2(z.x, w1.x, acc[4]);  acc[5]  = ffma2(z.y, w1.x, acc[5]);
        acc[6] = ffma2(z.x, w1.y, acc[6]);  acc[7]  = ffma2(z.y, w1.y, acc[7]);
        acc[8] = ffma2(z.x, w2.x, acc[8]);  acc[9]  = ffma2(z.y, w2.x, acc[9]);
        acc[10]= ffma2(z.x, w2.y, acc[10]); acc[11] = ffma2(z.y, w2.y, acc[11]);
        acc[12]= ffma2(z.x, w3.x, acc[12]); acc[13] = ffma2(z.y, w3.x, acc[13]);
        acc[14]= ffma2(z.x, w3.y, acc[14]); acc[15] = ffma2(z.y, w3.y, acc[15]);
    }
#pragma unroll
    for (int o = 0; o < 8; o++){
        float b = HASB ? bias[og*8+o] : 0.f;
#pragma unroll
        for (int p = 0; p < 2; p++){
            unsigned long long A = acc[o*2+p];
            float lo = f2lo(A) + b;
            float hi = f2hi(A) + b;
            if (ACT){ lo = lrelu(lo); hi = lrelu(hi); }
            *reinterpret_cast<float2*>(Zout + (og*8+o)*128 + eg*4 + p*2) = make_float2(lo, hi);
        }
    }
}

// Final 64->10 layer on a 128-row tile: e = tid&127, kh = tid>>7 (k-half).
__device__ __forceinline__ void layer10(const float* Zin, const float* wsh,
                                        float* part, int e, int kh)
{
    unsigned long long acc[5];
#pragma unroll
    for (int p = 0; p < 5; p++) acc[p] = 0ULL;
    const int k0 = kh*32;
#pragma unroll 4
    for (int kk = 0; kk < 32; kk++){
        int k = k0 + kk;
        unsigned long long z2 = splat2(Zin[k*128+e]);
        const float* wr = wsh + k*10;
#pragma unroll
        for (int p = 0; p < 5; p++){
            unsigned long long w = *reinterpret_cast<const unsigned long long*>(wr + p*2);
            acc[p] = ffma2(z2, w, acc[p]);
        }
    }
    float* pr = part + kh*1280 + e*10;
#pragma unroll
    for (int p = 0; p < 5; p++){ pr[p*2] = f2lo(acc[p]); pr[p*2+1] = f2hi(acc[p]); }
}

__device__ __forceinline__ void splatW(const float* __restrict__ W, float* Wsp, int tid){
    for (int idx = tid; idx < 4096; idx += 256){
        float w = W[idx];
        int k = idx >> 6, o = idx & 63;
        *reinterpret_cast<float2*>(Wsp + k*128 + o*2) = make_float2(w, w);
    }
}

// ---------------------------------------------------------------------------
// K2: per-node — u = hg@We0 (store), vp = MLP(hg) -> diagonal 4x4 blocks of X
// 128 nodes per block, 256 threads, grid 320
// ---------------------------------------------------------------------------
#define K2_SMEM_FLOATS 27856
__global__ __launch_bounds__(256,1) void node_kernel(
    const float* __restrict__ hg,
    const float* __restrict__ Wn0, const float* __restrict__ bn0,
    const float* __restrict__ Wn1, const float* __restrict__ bn1,
    const float* __restrict__ Wn2, const float* __restrict__ bn2,
    const float* __restrict__ We0,
    float* __restrict__ Xout)
{
    extern __shared__ float sm[];
    float* Z0   = sm;             // 8192
    float* Za   = sm + 8192;      // 8192
    float* Wsp  = sm + 16384;     // 8192
    float* wsh  = sm + 24576;     // 640
    float* part = sm + 25216;     // 2560
    float* bsh  = sm + 27776;     // 64
    float* b2   = sm + 27840;     // 16

    const int tid = threadIdx.x;
    const int e  = tid & 127, kh = tid >> 7;
    const int eg = tid & 31,  og = tid >> 5;
    const int r0 = blockIdx.x * 128;

    // transpose-load: Z0[k][e] = hg[r0+e][k]
    {
        const float4* row = reinterpret_cast<const float4*>(hg + (size_t)(r0+e)*64);
#pragma unroll
        for (int q = 0; q < 8; q++){
            float4 v = row[kh*8+q];
            int k = kh*32 + q*4;
            Z0[(k+0)*128+e]=v.x; Z0[(k+1)*128+e]=v.y; Z0[(k+2)*128+e]=v.z; Z0[(k+3)*128+e]=v.w;
        }
    }
    splatW(We0, Wsp, tid);
    __syncthreads();
    gemm128<false,false>(Z0, Za, Wsp, nullptr, eg, og);   // u (no bias/act)
    __syncthreads();
    {
        float4* urow = reinterpret_cast<float4*>(g_u + (size_t)(r0+e)*64);
#pragma unroll
        for (int q = 0; q < 8; q++){
            int k = kh*32 + q*4;
            urow[kh*8+q] = make_float4(Za[k*128+e], Za[(k+1)*128+e], Za[(k+2)*128+e], Za[(k+3)*128+e]);
        }
    }
    __syncthreads();
    splatW(Wn0, Wsp, tid);
    for (int i2 = tid; i2 < 64; i2 += 256) bsh[i2] = bn0[i2];
    __syncthreads();
    gemm128<true,true>(Z0, Za, Wsp, bsh, eg, og);
    __syncthreads();
    splatW(Wn1, Wsp, tid);
    for (int i2 = tid; i2 < 64; i2 += 256) bsh[i2] = bn1[i2];
    __syncthreads();
    gemm128<true,true>(Za, Z0, Wsp, bsh, eg, og);
    __syncthreads();
    for (int i2 = tid; i2 < 640; i2 += 256) wsh[i2] = Wn2[i2];
    if (tid < 10) b2[tid] = bn2[tid];
    __syncthreads();
    layer10(Z0, wsh, part, e, kh);
    __syncthreads();

    // diagonal 4x4 blocks: X[g, i*4+a, i*4 .. i*4+3]; 128 rows x 4 a = 512 stores
#pragma unroll
    for (int p = 0; p < 2; p++){
        int idx = tid + p*256;             // 0..511
        int n = idx >> 2, a = idx & 3;
        int r = r0 + n, gg = r/40, i = r - gg*40;
        const float* p0 = part + n*10;
        const float* p1 = part + 1280 + n*10;
        int s0=c_smat[a*4], s1=c_smat[a*4+1], s2=c_smat[a*4+2], s3=c_smat[a*4+3];
        float4 v = make_float4(p0[s0]+p1[s0]+b2[s0], p0[s1]+p1[s1]+b2[s1],
                               p0[s2]+p1[s2]+b2[s2], p0[s3]+p1[s3]+b2[s3]);
        *reinterpret_cast<float4*>(Xout + (size_t)gg*X_PER_G + (i*4+a)*160 + i*4) = v;
    }
}

// ---------------------------------------------------------------------------
// K3: per-edge — one block per group (grid 1024, 256 threads). Loads u rows +
// weights ONCE, then loops over 7 tiles of 128 edges:
//   z1 = lrelu(u_i+u_j+be0); z2 = lrelu(z1@We1+be1); ep = z2@We2+be2;
//   write symmetric 4x4 blocks to X at (i,j) and (j,i).
// ---------------------------------------------------------------------------
#define K3_SMEM_FLOATS 30784
__global__ __launch_bounds__(256,1) void edge_kernel(
    const int* __restrict__ ud,   /* int32 pairs (i,j) */
    const float* __restrict__ be0,
    const float* __restrict__ We1, const float* __restrict__ be1,
    const float* __restrict__ We2, const float* __restrict__ be2,
    float* __restrict__ Xout)
{
    extern __shared__ float sm[];
    float* ug   = sm;              // 40*65 = 2600 (pad 2608)
    float* Z0   = sm + 2608;       // 8192
    float* Za   = sm + 10800;      // 8192
    float* Wsp  = sm + 18992;      // 8192
    float* wsh  = sm + 27184;      // 640
    float* part = sm + 27824;      // 2560
    float* b0   = sm + 30384;      // 64
    float* b1   = sm + 30448;      // 64
    float* b2   = sm + 30512;      // 16
    int*   si   = (int*)(sm + 30528); // 128
    int*   sj   = (int*)(sm + 30656); // 128

    const int tid = threadIdx.x;
    const int e  = tid & 127, kh = tid >> 7;
    const int eg = tid & 31,  og = tid >> 5;
    const int g = blockIdx.x;

    {   // group's u rows into shared, stride 65 (conflict-free later reads)
        const float* usrc = g_u + (size_t)g*NN*64;
        for (int idx = tid; idx < NN*64; idx += 256){
            int n = idx >> 6, k = idx & 63;
            ug[n*65+k] = usrc[idx];
        }
    }
    splatW(We1, Wsp, tid);
    for (int i2 = tid; i2 < 64; i2 += 256){ b0[i2] = be0[i2]; b1[i2] = be1[i2]; }
    for (int i2 = tid; i2 < 640; i2 += 256) wsh[i2] = We2[i2];
    if (tid < 10) b2[tid] = be2[tid];

    float* Xg = Xout + (size_t)g*X_PER_G;

    for (int tile = 0; tile < 7; tile++){
        const int m0 = tile*128;
        const int ecnt = min(128, M_EDGES - m0);

        if (tid < 128){
            int ii = 0, jj = 0;
            if (tid < ecnt){ ii = ud[2*(m0+tid)]; jj = ud[2*(m0+tid)+1]; }
            si[tid] = ii; sj[tid] = jj;
        }
        __syncthreads();

        {   // z1
            const bool valid = e < ecnt;
            const int i = si[e], j = sj[e];
            const float* ui = ug + i*65;
            const float* uj = ug + j*65;
            for (int k = kh*32; k < kh*32+32; k++){
                float v = 0.f;
                if (valid) v = lrelu(ui[k] + uj[k] + b0[k]);
                Z0[k*128+e] = v;
            }
        }
        __syncthreads();
        gemm128<true,true>(Z0, Za, Wsp, b1, eg, og);
        __syncthreads();
        layer10(Za, wsh, part, e, kh);
        __syncthreads();

#pragma unroll
        for (int p = 0; p < 4; p++){
            int idx = tid + p*256;              // 0..1023
            int ee = idx >> 3, side = (idx >> 2) & 1, a = idx & 3;
            if (ee < ecnt){
                int i = si[ee], j = sj[ee];
                const float* p0 = part + ee*10;
                const float* p1 = part + 1280 + ee*10;
                int s0=c_smat[a*4], s1=c_smat[a*4+1], s2=c_smat[a*4+2], s3=c_smat[a*4+3];
                float4 v = make_float4(p0[s0]+p1[s0]+b2[s0], p0[s1]+p1[s1]+b2[s1],
                                       p0[s2]+p1[s2]+b2[s2], p0[s3]+p1[s3]+b2[s3]);
                int bi = side ? j : i;
                int bj = side ? i : j;
                *reinterpret_cast<float4*>(Xg + (bi*4+a)*160 + bj*4) = v;
            }
        }
        __syncthreads();
    }
}

// ---------------------------------------------------------------------------
extern "C" void kernel_launch(void* const* d_in, const int* in_sizes, int n_in,
                              void* d_out, int out_size)
{
    const float* x  = (const float*)d_in[0];
    // d_in[1] edge_index (unused: complete graph), d_in[3] edge_map (unused)
    const int*   ud = (const int*)d_in[2];   // int32 (JAX default x64 disabled)
    const float* Wg0 = (const float*)d_in[4];  const float* bg0 = (const float*)d_in[5];
    const float* Wg1 = (const float*)d_in[6];  const float* bg1 = (const float*)d_in[7];
    const float* Wg2 = (const float*)d_in[8];  const float* bg2 = (const float*)d_in[9];
    const float* Wn0 = (const float*)d_in[10]; const float* bn0 = (const float*)d_in[11];
    const float* Wn1 = (const float*)d_in[12]; const float* bn1 = (const float*)d_in[13];
    const float* Wn2 = (const float*)d_in[14]; const float* bn2 = (const float*)d_in[15];
    const float* We0 = (const float*)d_in[16]; const float* be0 = (const float*)d_in[17];
    const float* We1 = (const float*)d_in[18]; const float* be1 = (const float*)d_in[19];
    const float* We2 = (const float*)d_in[20]; const float* be2 = (const float*)d_in[21];

    // Adaptive output layout: reference returns (h, X).
    float* hout;
    float* Xout;
    size_t osz = (size_t)out_size;
    if (osz >= (size_t)H_ELEMS + X_ELEMS){
        hout = (float*)d_out;
        Xout = (float*)d_out + H_ELEMS;
    } else if (osz >= X_ELEMS){
        cudaGetSymbolAddress((void**)&hout, g_h);
        Xout = (float*)d_out;
    } else {
        hout = (float*)d_out;
        cudaGetSymbolAddress((void**)&Xout, g_x);
    }

    cudaFuncSetAttribute(node_kernel, cudaFuncAttributeMaxDynamicSharedMemorySize,
                         K2_SMEM_FLOATS*4);
    cudaFuncSetAttribute(edge_kernel, cudaFuncAttributeMaxDynamicSharedMemorySize,
                         K3_SMEM_FLOATS*4);

    gcn_kernel<<<NG, 128>>>(x, Wg0, bg0, Wg1, bg1, Wg2, bg2, hout);
    node_kernel<<<NODES/128, 256, K2_SMEM_FLOATS*4>>>(hout, Wn0, bn0, Wn1, bn1,
                                                      Wn2, bn2, We0, Xout);
    edge_kernel<<<NG, 256, K3_SMEM_FLOATS*4>>>(ud, be0, We1, be1,
                                               We2, be2, Xout);
}

// round 7
// speedup vs baseline: 2.0359x; 2.0359x over previous
#include <cuda_runtime.h>

#define NG 1024
#define NN 40
#define M_EDGES 780
#define NODES (NG*NN)          /* 40960 */
#define H_ELEMS (NODES*64)     /* 2621440 */
#define X_PER_G (160*160)      /* 25600 */
#define X_ELEMS ((size_t)NG*X_PER_G)

// scratch: u = hg @ We0 per node (10.5 MB, L2-resident)
__device__ float g_u[NODES * 64];
// fallback scratch if the harness's d_out does not cover h and/or X
__device__ float g_h[H_ELEMS];
__device__ float g_x[NG * X_PER_G];

__constant__ int c_smat[16] = {0,1,2,3, 1,4,5,6, 2,5,7,8, 3,6,8,9};

__device__ __forceinline__ float lrelu(float v){ return v > 0.f ? v : 0.1f*v; }

typedef unsigned long long ull;

// packed fp32x2 FMA (sm_10x)
__device__ __forceinline__ ull ffma2(ull a, ull b, ull c){
    ull d;
    asm("fma.rn.f32x2 %0, %1, %2, %3;" : "=l"(d) : "l"(a), "l"(b), "l"(c));
    return d;
}
__device__ __forceinline__ ull splat2(float x){
    ull r;
    asm("mov.b64 %0, {%1, %1};" : "=l"(r) : "f"(x));
    return r;
}
__device__ __forceinline__ float f2lo(ull a){ return __uint_as_float((unsigned)(a & 0xffffffffULL)); }
__device__ __forceinline__ float f2hi(ull a){ return __uint_as_float((unsigned)(a >> 32)); }

// no-op kernels to shift the ncu -s 5 -c 1 sampling window onto the hot kernel
__global__ void dummy_kernel(){}

// ---------------------------------------------------------------------------
// K1: GCN — complete graph => gcn(h)[j] = (colsum(t) - t[j])/39 + b, t = h@W
// k-loops vectorized: weights transposed to [o][k] with pad-36 stride.
// ---------------------------------------------------------------------------
__global__ __launch_bounds__(128) void gcn_kernel(
    const float* __restrict__ x,
    const float* __restrict__ Wg0, const float* __restrict__ bg0,
    const float* __restrict__ Wg1, const float* __restrict__ bg1,
    const float* __restrict__ Wg2, const float* __restrict__ bg2,
    float* __restrict__ hout)
{
    __shared__ float sh[NN*64];      // activations [n][k] stride 64
    __shared__ float st[NN*64];      // t = h@W     [n][o] stride 64
    __shared__ float swt[64*36];     // W^T [o][k] stride 36 (pad: conflict-free)
    __shared__ float ssum[64];
    const int g = blockIdx.x, tid = threadIdx.x;

    for (int idx = tid; idx < NN*64; idx += 128) sh[idx] = 0.f;
    __syncthreads();
    for (int idx = tid; idx < NN*6; idx += 128){
        int n = idx/6, c = idx - n*6;
        sh[n*64+c] = x[(g*NN+n)*16 + c];
    }
    __syncthreads();

    auto finish = [&](int outd, const float* b, bool act){
        for (int o = tid; o < outd; o += 128){
            float s = 0.f;
            for (int n = 0; n < NN; n++) s += st[n*64+o];
            ssum[o] = s;
        }
        __syncthreads();
        const float inv = 1.f/39.f;
        for (int idx = tid; idx < NN*outd; idx += 128){
            int n = idx/outd, o = idx - n*outd;
            float v = (ssum[o] - st[n*64+o])*inv + b[o];
            if (act) v = lrelu(v);
            sh[n*64+o] = v;
        }
        __syncthreads();
    };

    // layer 0: ind=6 (scalar, tiny)
    {
        for (int idx = tid; idx < 6*32; idx += 128) swt[idx] = Wg0[idx]; // [k][o]
        __syncthreads();
        for (int idx = tid; idx < NN*32; idx += 128){
            int n = idx/32, o = idx & 31;
            float a = 0.f;
#pragma unroll
            for (int k = 0; k < 6; k++) a += sh[n*64+k]*swt[k*32+o];
            st[n*64+o] = a;
        }
        __syncthreads();
        finish(32, bg0, true);
    }

    auto layerV = [&](const float* W, const float* b, int outd, bool act){
        for (int idx = tid; idx < 32*outd; idx += 128){
            int k = idx / outd, o = idx - k*outd;
            swt[o*36 + k] = W[idx];
        }
        __syncthreads();
        for (int idx = tid; idx < NN*outd; idx += 128){
            int n = idx/outd, o = idx - n*outd;
            const float4* A = reinterpret_cast<const float4*>(sh + n*64);
            const float4* B = reinterpret_cast<const float4*>(swt + o*36);
            float ax=0.f, ay=0.f, az=0.f, aw=0.f;
#pragma unroll
            for (int q = 0; q < 8; q++){
                float4 a = A[q], w = B[q];
                ax += a.x*w.x; ay += a.y*w.y; az += a.z*w.z; aw += a.w*w.w;
            }
            st[n*64+o] = (ax+ay)+(az+aw);
        }
        __syncthreads();
        finish(outd, b, act);
    };
    layerV(Wg1, bg1, 32, true);
    layerV(Wg2, bg2, 64, false);

    float* hrow = hout + (size_t)g*NN*64;
    for (int idx = tid; idx < NN*64; idx += 128) hrow[idx] = sh[idx];
}

// ---------------------------------------------------------------------------
// 128x64x64 GEMM tile, 256 threads, thread tile = 4 rows x 8 outs.
// Weights PLAIN in smem [k][o] (64x64); splat to f32x2 in registers.
// Zin: [k][e] stride 128.  Zout: [o][e] stride 128.  INPLACE => Zout==Zin
// (internal barrier between last read and first write).
// ---------------------------------------------------------------------------
template<bool ACT, bool HASB, bool INPLACE>
__device__ __forceinline__ void gemmR(const float* Zin, float* Zout,
                                      const float* Wsm, const float* bias,
                                      int eg, int og)
{
    ull acc[16];
#pragma unroll
    for (int i = 0; i < 16; i++) acc[i] = 0ULL;

#pragma unroll 2
    for (int k = 0; k < 64; k++){
        ulonglong2 z = *reinterpret_cast<const ulonglong2*>(Zin + k*128 + eg*4);
        float4 wa = *reinterpret_cast<const float4*>(Wsm + k*64 + og*8);
        float4 wb = *reinterpret_cast<const float4*>(Wsm + k*64 + og*8 + 4);
        ull w0 = splat2(wa.x), w1 = splat2(wa.y), w2 = splat2(wa.z), w3 = splat2(wa.w);
        ull w4 = splat2(wb.x), w5 = splat2(wb.y), w6 = splat2(wb.z), w7 = splat2(wb.w);
        acc[0] = ffma2(z.x, w0, acc[0]);  acc[1]  = ffma2(z.y, w0, acc[1]);
        acc[2] = ffma2(z.x, w1, acc[2]);  acc[3]  = ffma2(z.y, w1, acc[3]);
        acc[4] = ffma2(z.x, w2, acc[4]);  acc[5]  = ffma2(z.y, w2, acc[5]);
        acc[6] = ffma2(z.x, w3, acc[6]);  acc[7]  = ffma2(z.y, w3, acc[7]);
        acc[8] = ffma2(z.x, w4, acc[8]);  acc[9]  = ffma2(z.y, w4, acc[9]);
        acc[10]= ffma2(z.x, w5, acc[10]); acc[11] = ffma2(z.y, w5, acc[11]);
        acc[12]= ffma2(z.x, w6, acc[12]); acc[13] = ffma2(z.y, w6, acc[13]);
        acc[14]= ffma2(z.x, w7, acc[14]); acc[15] = ffma2(z.y, w7, acc[15]);
    }
    if (INPLACE) __syncthreads();
#pragma unroll
    for (int o = 0; o < 8; o++){
        float b = HASB ? bias[og*8+o] : 0.f;
#pragma unroll
        for (int p = 0; p < 2; p++){
            ull A = acc[o*2+p];
            float lo = f2lo(A) + b;
            float hi = f2hi(A) + b;
            if (ACT){ lo = lrelu(lo); hi = lrelu(hi); }
            *reinterpret_cast<float2*>(Zout + (og*8+o)*128 + eg*4 + p*2) = make_float2(lo, hi);
        }
    }
}

// Final 64->10 layer on a 128-row tile: e = tid&127, kh = tid>>7 (k-half).
__device__ __forceinline__ void layer10(const float* Zin, const float* wsh,
                                        float* part, int e, int kh)
{
    ull acc[5];
#pragma unroll
    for (int p = 0; p < 5; p++) acc[p] = 0ULL;
    const int k0 = kh*32;
#pragma unroll 4
    for (int kk = 0; kk < 32; kk++){
        int k = k0 + kk;
        ull z2 = splat2(Zin[k*128+e]);
        const float* wr = wsh + k*10;
#pragma unroll
        for (int p = 0; p < 5; p++){
            ull w = *reinterpret_cast<const ull*>(wr + p*2);
            acc[p] = ffma2(z2, w, acc[p]);
        }
    }
    float* pr = part + kh*1280 + e*10;
#pragma unroll
    for (int p = 0; p < 5; p++){ pr[p*2] = f2lo(acc[p]); pr[p*2+1] = f2hi(acc[p]); }
}

// ---------------------------------------------------------------------------
// K2: per-node — u = hg@We0 (store), vp = MLP(hg) -> diagonal 4x4 blocks of X
// 128 nodes per block, 256 threads, grid 320. smem ~95KB -> 2 blocks/SM.
// ---------------------------------------------------------------------------
#define K2_SMEM_FLOATS 23760
__global__ __launch_bounds__(256) void node_kernel(
    const float* __restrict__ hg,
    const float* __restrict__ Wn0, const float* __restrict__ bn0,
    const float* __restrict__ Wn1, const float* __restrict__ bn1,
    const float* __restrict__ Wn2, const float* __restrict__ bn2,
    const float* __restrict__ We0,
    float* __restrict__ Xout)
{
    extern __shared__ float sm[];
    float* Z0   = sm;             // 8192
    float* Za   = sm + 8192;      // 8192
    float* Wsm  = sm + 16384;     // 4096
    float* wsh  = sm + 20480;     // 640
    float* part = sm + 21120;     // 2560
    float* bsh  = sm + 23680;     // 64
    float* b2   = sm + 23744;     // 16

    const int tid = threadIdx.x;
    const int e  = tid & 127, kh = tid >> 7;
    const int eg = tid & 31,  og = tid >> 5;
    const int r0 = blockIdx.x * 128;

    // transpose-load: Z0[k][e] = hg[r0+e][k]; load We0
    {
        const float4* row = reinterpret_cast<const float4*>(hg + (size_t)(r0+e)*64);
#pragma unroll
        for (int q = 0; q < 8; q++){
            float4 v = row[kh*8+q];
            int k = kh*32 + q*4;
            Z0[(k+0)*128+e]=v.x; Z0[(k+1)*128+e]=v.y; Z0[(k+2)*128+e]=v.z; Z0[(k+3)*128+e]=v.w;
        }
    }
    for (int i2 = tid; i2 < 4096; i2 += 256) Wsm[i2] = We0[i2];
    __syncthreads();
    gemmR<false,false,false>(Z0, Za, Wsm, nullptr, eg, og);   // u
    __syncthreads();
    {   // store u; concurrently load Wn0 (Wsm free after sync)
        float4* urow = reinterpret_cast<float4*>(g_u + (size_t)(r0+e)*64);
#pragma unroll
        for (int q = 0; q < 8; q++){
            int k = kh*32 + q*4;
            urow[kh*8+q] = make_float4(Za[k*128+e], Za[(k+1)*128+e], Za[(k+2)*128+e], Za[(k+3)*128+e]);
        }
    }
    for (int i2 = tid; i2 < 4096; i2 += 256) Wsm[i2] = Wn0[i2];
    for (int i2 = tid; i2 < 64; i2 += 256) bsh[i2] = bn0[i2];
    __syncthreads();
    gemmR<true,true,false>(Z0, Za, Wsm, bsh, eg, og);
    __syncthreads();
    for (int i2 = tid; i2 < 4096; i2 += 256) Wsm[i2] = Wn1[i2];
    for (int i2 = tid; i2 < 64; i2 += 256) bsh[i2] = bn1[i2];
    __syncthreads();
    gemmR<true,true,false>(Za, Z0, Wsm, bsh, eg, og);
    __syncthreads();
    for (int i2 = tid; i2 < 640; i2 += 256) wsh[i2] = Wn2[i2];
    if (tid < 10) b2[tid] = bn2[tid];
    __syncthreads();
    layer10(Z0, wsh, part, e, kh);
    __syncthreads();

    // diagonal 4x4 blocks
#pragma unroll
    for (int p = 0; p < 2; p++){
        int idx = tid + p*256;             // 0..511
        int n = idx >> 2, a = idx & 3;
        int r = r0 + n, gg = r/40, i = r - gg*40;
        const float* p0 = part + n*10;
        const float* p1 = part + 1280 + n*10;
        int s0=c_smat[a*4], s1=c_smat[a*4+1], s2=c_smat[a*4+2], s3=c_smat[a*4+3];
        float4 v = make_float4(p0[s0]+p1[s0]+b2[s0], p0[s1]+p1[s1]+b2[s1],
                               p0[s2]+p1[s2]+b2[s2], p0[s3]+p1[s3]+b2[s3]);
        *reinterpret_cast<float4*>(Xout + (size_t)gg*X_PER_G + (i*4+a)*160 + i*4) = v;
    }
}

// ---------------------------------------------------------------------------
// K3: per-edge — 2 blocks per group (grid 2048, 256 threads). Tiles of 128
// edges, interleaved between the two blocks. smem ~74KB -> 2 blocks/SM.
//   z1 = lrelu(u_i+u_j+be0); z2 = lrelu(z1@We1+be1) IN-PLACE; ep = z2@We2+be2;
//   write symmetric 4x4 blocks to X at (i,j) and (j,i).
// ---------------------------------------------------------------------------
#define K3_SMEM_FLOATS 18496
__global__ __launch_bounds__(256) void edge_kernel(
    const int* __restrict__ ud,   /* int32 pairs (i,j) */
    const float* __restrict__ be0,
    const float* __restrict__ We1, const float* __restrict__ be1,
    const float* __restrict__ We2, const float* __restrict__ be2,
    float* __restrict__ Xout)
{
    extern __shared__ float sm[];
    float* ug   = sm;              // 40*65 = 2600 (pad 2608)
    float* Z0   = sm + 2608;       // 8192
    float* Wsm  = sm + 10800;      // 4096
    float* wsh  = sm + 14896;      // 640
    float* part = sm + 15536;      // 2560
    float* b0   = sm + 18096;      // 64
    float* b1   = sm + 18160;      // 64
    float* b2   = sm + 18224;      // 16
    int*   si   = (int*)(sm + 18240); // 128
    int*   sj   = (int*)(sm + 18368); // 128

    const int tid = threadIdx.x;
    const int e  = tid & 127, kh = tid >> 7;
    const int eg = tid & 31,  og = tid >> 5;
    const int g    = blockIdx.x >> 1;
    const int half = blockIdx.x & 1;

    {   // group's u rows into shared, stride 65
        const float* usrc = g_u + (size_t)g*NN*64;
        for (int idx = tid; idx < NN*64; idx += 256){
            int n = idx >> 6, k = idx & 63;
            ug[n*65+k] = usrc[idx];
        }
    }
    for (int i2 = tid; i2 < 4096; i2 += 256) Wsm[i2] = We1[i2];
    for (int i2 = tid; i2 < 64; i2 += 256){ b0[i2] = be0[i2]; b1[i2] = be1[i2]; }
    for (int i2 = tid; i2 < 640; i2 += 256) wsh[i2] = We2[i2];
    if (tid < 10) b2[tid] = be2[tid];

    float* Xg = Xout + (size_t)g*X_PER_G;

    for (int tile = half; tile < 7; tile += 2){
        const int m0 = tile*128;
        const int ecnt = min(128, M_EDGES - m0);

        __syncthreads();   // prev scatter done reading si/sj; setup visible (1st iter)
        if (tid < 128){
            int2 p = make_int2(0,0);
            if (tid < ecnt) p = *reinterpret_cast<const int2*>(ud + 2*(m0+tid));
            si[tid] = p.x; sj[tid] = p.y;
        }
        __syncthreads();

        {   // z1 -> Z0
            const bool valid = e < ecnt;
            const int i = si[e], j = sj[e];
            const float* ui = ug + i*65;
            const float* uj = ug + j*65;
            for (int k = kh*32; k < kh*32+32; k++){
                float v = 0.f;
                if (valid) v = lrelu(ui[k] + uj[k] + b0[k]);
                Z0[k*128+e] = v;
            }
        }
        __syncthreads();
        gemmR<true,true,true>(Z0, Z0, Wsm, b1, eg, og);   // in-place
        __syncthreads();
        layer10(Z0, wsh, part, e, kh);
        __syncthreads();

#pragma unroll
        for (int p = 0; p < 4; p++){
            int idx = tid + p*256;              // 0..1023
            int ee = idx >> 3, side = (idx >> 2) & 1, a = idx & 3;
            if (ee < ecnt){
                int i = si[ee], j = sj[ee];
                const float* p0 = part + ee*10;
                const float* p1 = part + 1280 + ee*10;
                int s0=c_smat[a*4], s1=c_smat[a*4+1], s2=c_smat[a*4+2], s3=c_smat[a*4+3];
                float4 v = make_float4(p0[s0]+p1[s0]+b2[s0], p0[s1]+p1[s1]+b2[s1],
                                       p0[s2]+p1[s2]+b2[s2], p0[s3]+p1[s3]+b2[s3]);
                int bi = side ? j : i;
                int bj = side ? i : j;
                *reinterpret_cast<float4*>(Xg + (bi*4+a)*160 + bj*4) = v;
            }
        }
    }
}

// ---------------------------------------------------------------------------
extern "C" void kernel_launch(void* const* d_in, const int* in_sizes, int n_in,
                              void* d_out, int out_size)
{
    const float* x  = (const float*)d_in[0];
    // d_in[1] edge_index (unused: complete graph), d_in[3] edge_map (unused)
    const int*   ud = (const int*)d_in[2];   // int32 (JAX default x64 disabled)
    const float* Wg0 = (const float*)d_in[4];  const float* bg0 = (const float*)d_in[5];
    const float* Wg1 = (const float*)d_in[6];  const float* bg1 = (const float*)d_in[7];
    const float* Wg2 = (const float*)d_in[8];  const float* bg2 = (const float*)d_in[9];
    const float* Wn0 = (const float*)d_in[10]; const float* bn0 = (const float*)d_in[11];
    const float* Wn1 = (const float*)d_in[12]; const float* bn1 = (const float*)d_in[13];
    const float* Wn2 = (const float*)d_in[14]; const float* bn2 = (const float*)d_in[15];
    const float* We0 = (const float*)d_in[16]; const float* be0 = (const float*)d_in[17];
    const float* We1 = (const float*)d_in[18]; const float* be1 = (const float*)d_in[19];
    const float* We2 = (const float*)d_in[20]; const float* be2 = (const float*)d_in[21];

    // Adaptive output layout: reference returns (h, X).
    float* hout;
    float* Xout;
    size_t osz = (size_t)out_size;
    if (osz >= (size_t)H_ELEMS + X_ELEMS){
        hout = (float*)d_out;
        Xout = (float*)d_out + H_ELEMS;
    } else if (osz >= X_ELEMS){
        cudaGetSymbolAddress((void**)&hout, g_h);
        Xout = (float*)d_out;
    } else {
        hout = (float*)d_out;
        cudaGetSymbolAddress((void**)&Xout, g_x);
    }

    cudaFuncSetAttribute(node_kernel, cudaFuncAttributeMaxDynamicSharedMemorySize,
                         K2_SMEM_FLOATS*4);
    cudaFuncSetAttribute(edge_kernel, cudaFuncAttributeMaxDynamicSharedMemorySize,
                         K3_SMEM_FLOATS*4);

    dummy_kernel<<<1, 32>>>();
    dummy_kernel<<<1, 32>>>();
    gcn_kernel<<<NG, 128>>>(x, Wg0, bg0, Wg1, bg1, Wg2, bg2, hout);
    node_kernel<<<NODES/128, 256, K2_SMEM_FLOATS*4>>>(hout, Wn0, bn0, Wn1, bn1,
                                                      Wn2, bn2, We0, Xout);
    edge_kernel<<<NG*2, 256, K3_SMEM_FLOATS*4>>>(ud, be0, We1, be1,
                                                 We2, be2, Xout);
}

// round 9
// speedup vs baseline: 2.1988x; 1.0800x over previous
#include <cuda_runtime.h>

#define NG 1024
#define NN 40
#define M_EDGES 780
#define NODES (NG*NN)          /* 40960 */
#define H_ELEMS (NODES*64)     /* 2621440 */
#define X_PER_G (160*160)      /* 25600 */
#define X_ELEMS ((size_t)NG*X_PER_G)

// scratch: u = hg @ We0 per node (10.5 MB, L2-resident)
__device__ float g_u[NODES * 64];
// fallback scratch if the harness's d_out does not cover h and/or X
__device__ float g_h[H_ELEMS];
__device__ float g_x[NG * X_PER_G];

__constant__ int c_smat[16] = {0,1,2,3, 1,4,5,6, 2,5,7,8, 3,6,8,9};

__device__ __forceinline__ float lrelu(float v){ return v > 0.f ? v : 0.1f*v; }

typedef unsigned long long ull;

// packed fp32x2 FMA (sm_10x): 2 MACs per instruction, fp32-peak path
__device__ __forceinline__ ull ffma2(ull a, ull b, ull c){
    ull d;
    asm("fma.rn.f32x2 %0, %1, %2, %3;" : "=l"(d) : "l"(a), "l"(b), "l"(c));
    return d;
}
__device__ __forceinline__ ull splat2(float x){
    ull r;
    asm("mov.b64 %0, {%1, %1};" : "=l"(r) : "f"(x));
    return r;
}
__device__ __forceinline__ float f2lo(ull a){ return __uint_as_float((unsigned)(a & 0xffffffffULL)); }
__device__ __forceinline__ float f2hi(ull a){ return __uint_as_float((unsigned)(a >> 32)); }

// no-op kernels to shift the ncu -s 5 -c 1 sampling window onto the hot kernel
__global__ void dummy_kernel(){}

// ---------------------------------------------------------------------------
// K1: GCN — complete graph => gcn(h)[j] = (colsum(t) - t[j])/39 + b, t = h@W
// ---------------------------------------------------------------------------
__global__ __launch_bounds__(128) void gcn_kernel(
    const float* __restrict__ x,
    const float* __restrict__ Wg0, const float* __restrict__ bg0,
    const float* __restrict__ Wg1, const float* __restrict__ bg1,
    const float* __restrict__ Wg2, const float* __restrict__ bg2,
    float* __restrict__ hout)
{
    __shared__ float sh[NN*64];      // activations [n][k] stride 64
    __shared__ float st[NN*64];      // t = h@W     [n][o] stride 64
    __shared__ float swt[64*36];     // W^T [o][k] stride 36 (pad: conflict-free)
    __shared__ float ssum[64];
    const int g = blockIdx.x, tid = threadIdx.x;

    for (int idx = tid; idx < NN*64; idx += 128) sh[idx] = 0.f;
    __syncthreads();
    for (int idx = tid; idx < NN*6; idx += 128){
        int n = idx/6, c = idx - n*6;
        sh[n*64+c] = x[(g*NN+n)*16 + c];
    }
    __syncthreads();

    auto finish = [&](int outd, const float* b, bool act){
        for (int o = tid; o < outd; o += 128){
            float s = 0.f;
            for (int n = 0; n < NN; n++) s += st[n*64+o];
            ssum[o] = s;
        }
        __syncthreads();
        const float inv = 1.f/39.f;
        for (int idx = tid; idx < NN*outd; idx += 128){
            int n = idx/outd, o = idx - n*outd;
            float v = (ssum[o] - st[n*64+o])*inv + b[o];
            if (act) v = lrelu(v);
            sh[n*64+o] = v;
        }
        __syncthreads();
    };

    // layer 0: ind=6 (scalar, tiny)
    {
        for (int idx = tid; idx < 6*32; idx += 128) swt[idx] = Wg0[idx]; // [k][o]
        __syncthreads();
        for (int idx = tid; idx < NN*32; idx += 128){
            int n = idx/32, o = idx & 31;
            float a = 0.f;
#pragma unroll
            for (int k = 0; k < 6; k++) a += sh[n*64+k]*swt[k*32+o];
            st[n*64+o] = a;
        }
        __syncthreads();
        finish(32, bg0, true);
    }

    auto layerV = [&](const float* W, const float* b, int outd, bool act){
        for (int idx = tid; idx < 32*outd; idx += 128){
            int k = idx / outd, o = idx - k*outd;
            swt[o*36 + k] = W[idx];
        }
        __syncthreads();
        for (int idx = tid; idx < NN*outd; idx += 128){
            int n = idx/outd, o = idx - n*outd;
            const float4* A = reinterpret_cast<const float4*>(sh + n*64);
            const float4* B = reinterpret_cast<const float4*>(swt + o*36);
            float ax=0.f, ay=0.f, az=0.f, aw=0.f;
#pragma unroll
            for (int q = 0; q < 8; q++){
                float4 a = A[q], w = B[q];
                ax += a.x*w.x; ay += a.y*w.y; az += a.z*w.z; aw += a.w*w.w;
            }
            st[n*64+o] = (ax+ay)+(az+aw);
        }
        __syncthreads();
        finish(outd, b, act);
    };
    layerV(Wg1, bg1, 32, true);
    layerV(Wg2, bg2, 64, false);

    float* hrow = hout + (size_t)g*NN*64;
    for (int idx = tid; idx < NN*64; idx += 128) hrow[idx] = sh[idx];
}

// ---------------------------------------------------------------------------
// 128x64x64 GEMM mainloop, 256 threads, thread tile = 4 rows x 8 outs.
// z-splat scheme: weights load as raw contiguous f32x2 pairs (warp-uniform,
// broadcast), z values splatted in registers (4 movs/k).
// Zin: [k][e] stride 128. Wsm: [k][o] plain 64x64.
// acc[e*4+op] = f32x2 over outputs (og*8+2*op, og*8+2*op+1) for edge eg*4+e.
// ---------------------------------------------------------------------------
__device__ __forceinline__ void gemm_main(const float* Zin, const float* Wsm,
                                          int eg, int og, ull* acc)
{
#pragma unroll
    for (int i = 0; i < 16; i++) acc[i] = 0ULL;
#pragma unroll 4
    for (int k = 0; k < 64; k++){
        float4 z = *reinterpret_cast<const float4*>(Zin + k*128 + eg*4);
        ulonglong2 wA = *reinterpret_cast<const ulonglong2*>(Wsm + k*64 + og*8);
        ulonglong2 wB = *reinterpret_cast<const ulonglong2*>(Wsm + k*64 + og*8 + 4);
        ull z0 = splat2(z.x), z1 = splat2(z.y), z2 = splat2(z.z), z3 = splat2(z.w);
        acc[0] = ffma2(z0, wA.x, acc[0]);  acc[1]  = ffma2(z0, wA.y, acc[1]);
        acc[2] = ffma2(z0, wB.x, acc[2]);  acc[3]  = ffma2(z0, wB.y, acc[3]);
        acc[4] = ffma2(z1, wA.x, acc[4]);  acc[5]  = ffma2(z1, wA.y, acc[5]);
        acc[6] = ffma2(z1, wB.x, acc[6]);  acc[7]  = ffma2(z1, wB.y, acc[7]);
        acc[8] = ffma2(z2, wA.x, acc[8]);  acc[9]  = ffma2(z2, wA.y, acc[9]);
        acc[10]= ffma2(z2, wB.x, acc[10]); acc[11] = ffma2(z2, wB.y, acc[11]);
        acc[12]= ffma2(z3, wA.x, acc[12]); acc[13] = ffma2(z3, wB.x, acc[13]);
        acc[14]= ffma2(z3, wA.y, acc[14]); acc[15] = ffma2(z3, wB.y, acc[15]);
    }
}
// NOTE acc[12..15] ordering: e=3 -> op order {0,2,1,3}; epilogues index via opmap.
__device__ __forceinline__ int accidx(int e, int op){
    if (e < 3) return e*4 + op;
    const int m[4] = {12,14,13,15};
    return m[op];
}

// smem epilogue: Zout[o][e] stride 128; INPLACE barrier before writes.
template<bool ACT, bool INPLACE>
__device__ __forceinline__ void gemm_store_smem(float* Zout, const float* bias,
                                                int eg, int og, ull* acc)
{
    float b[8];
#pragma unroll
    for (int q = 0; q < 8; q++) b[q] = bias[og*8+q];
    if (INPLACE) __syncthreads();
#pragma unroll
    for (int e = 0; e < 4; e++){
#pragma unroll
        for (int op = 0; op < 4; op++){
            ull A = acc[accidx(e,op)];
            float lo = f2lo(A) + b[2*op];
            float hi = f2hi(A) + b[2*op+1];
            if (ACT){ lo = lrelu(lo); hi = lrelu(hi); }
            Zout[(og*8+2*op)*128   + eg*4+e] = lo;
            Zout[(og*8+2*op+1)*128 + eg*4+e] = hi;
        }
    }
}

// global epilogue: stream accumulators straight to g_u rows (no bias/act)
__device__ __forceinline__ void gemm_store_gu(float* gu, int r0,
                                              int eg, int og, ull* acc)
{
#pragma unroll
    for (int e = 0; e < 4; e++){
        int row = r0 + eg*4 + e;
        float4 v0 = make_float4(f2lo(acc[accidx(e,0)]), f2hi(acc[accidx(e,0)]),
                                f2lo(acc[accidx(e,1)]), f2hi(acc[accidx(e,1)]));
        float4 v1 = make_float4(f2lo(acc[accidx(e,2)]), f2hi(acc[accidx(e,2)]),
                                f2lo(acc[accidx(e,3)]), f2hi(acc[accidx(e,3)]));
        *reinterpret_cast<float4*>(gu + (size_t)row*64 + og*8)     = v0;
        *reinterpret_cast<float4*>(gu + (size_t)row*64 + og*8 + 4) = v1;
    }
}

// Final 64->10 layer on a 128-row tile: e = tid&127, kh = tid>>7 (k-half).
__device__ __forceinline__ void layer10(const float* Zin, const float* wsh,
                                        float* part, int e, int kh)
{
    ull acc[5];
#pragma unroll
    for (int p = 0; p < 5; p++) acc[p] = 0ULL;
    const int k0 = kh*32;
#pragma unroll 4
    for (int kk = 0; kk < 32; kk++){
        int k = k0 + kk;
        ull z2 = splat2(Zin[k*128+e]);
        const float* wr = wsh + k*10;
#pragma unroll
        for (int p = 0; p < 5; p++){
            ull w = *reinterpret_cast<const ull*>(wr + p*2);
            acc[p] = ffma2(z2, w, acc[p]);
        }
    }
    float* pr = part + kh*1280 + e*10;
#pragma unroll
    for (int p = 0; p < 5; p++){ pr[p*2] = f2lo(acc[p]); pr[p*2+1] = f2hi(acc[p]); }
}

// ---------------------------------------------------------------------------
// K2: per-node — u = hg@We0 (streamed to g_u), vp = MLP(hg) -> diag blocks.
// 128 nodes per block, 256 threads, grid 320. smem ~62KB -> 3 blocks/SM.
// ---------------------------------------------------------------------------
#define K2_SMEM_FLOATS 15568
__global__ __launch_bounds__(256, 3) void node_kernel(
    const float* __restrict__ hg,
    const float* __restrict__ Wn0, const float* __restrict__ bn0,
    const float* __restrict__ Wn1, const float* __restrict__ bn1,
    const float* __restrict__ Wn2, const float* __restrict__ bn2,
    const float* __restrict__ We0,
    float* __restrict__ Xout)
{
    extern __shared__ float sm[];
    float* Z0   = sm;             // 8192
    float* Wsm  = sm + 8192;      // 4096
    float* wsh  = sm + 12288;     // 640
    float* part = sm + 12928;     // 2560
    float* bsh  = sm + 15488;     // 64
    float* b2   = sm + 15552;     // 16

    const int tid = threadIdx.x;
    const int e  = tid & 127, kh = tid >> 7;
    const int eg = tid & 31,  og = tid >> 5;
    const int r0 = blockIdx.x * 128;
    ull acc[16];

    // transpose-load: Z0[k][e] = hg[r0+e][k]; load We0
    {
        const float4* row = reinterpret_cast<const float4*>(hg + (size_t)(r0+e)*64);
#pragma unroll
        for (int q = 0; q < 8; q++){
            float4 v = row[kh*8+q];
            int k = kh*32 + q*4;
            Z0[(k+0)*128+e]=v.x; Z0[(k+1)*128+e]=v.y; Z0[(k+2)*128+e]=v.z; Z0[(k+3)*128+e]=v.w;
        }
    }
    for (int i2 = tid; i2 < 4096; i2 += 256) Wsm[i2] = We0[i2];
    __syncthreads();
    gemm_main(Z0, Wsm, eg, og, acc);            // u = hg @ We0
    gemm_store_gu(g_u, r0, eg, og, acc);        // straight to global
    __syncthreads();
    for (int i2 = tid; i2 < 4096; i2 += 256) Wsm[i2] = Wn0[i2];
    for (int i2 = tid; i2 < 64; i2 += 256) bsh[i2] = bn0[i2];
    __syncthreads();
    gemm_main(Z0, Wsm, eg, og, acc);
    gemm_store_smem<true, true>(Z0, bsh, eg, og, acc);   // in-place
    __syncthreads();
    for (int i2 = tid; i2 < 4096; i2 += 256) Wsm[i2] = Wn1[i2];
    for (int i2 = tid; i2 < 64; i2 += 256) bsh[i2] = bn1[i2];
    __syncthreads();
    gemm_main(Z0, Wsm, eg, og, acc);
    gemm_store_smem<true, true>(Z0, bsh, eg, og, acc);   // in-place
    __syncthreads();
    for (int i2 = tid; i2 < 640; i2 += 256) wsh[i2] = Wn2[i2];
    if (tid < 10) b2[tid] = bn2[tid];
    __syncthreads();
    layer10(Z0, wsh, part, e, kh);
    __syncthreads();

    // diagonal 4x4 blocks
#pragma unroll
    for (int p = 0; p < 2; p++){
        int idx = tid + p*256;             // 0..511
        int n = idx >> 2, a = idx & 3;
        int r = r0 + n, gg = r/40, i = r - gg*40;
        const float* p0 = part + n*10;
        const float* p1 = part + 1280 + n*10;
        int s0=c_smat[a*4], s1=c_smat[a*4+1], s2=c_smat[a*4+2], s3=c_smat[a*4+3];
        float4 v = make_float4(p0[s0]+p1[s0]+b2[s0], p0[s1]+p1[s1]+b2[s1],
                               p0[s2]+p1[s2]+b2[s2], p0[s3]+p1[s3]+b2[s3]);
        *reinterpret_cast<float4*>(Xout + (size_t)gg*X_PER_G + (i*4+a)*160 + i*4) = v;
    }
}

// ---------------------------------------------------------------------------
// K3: per-edge — 2 blocks per group (grid 2048, 256 threads), 74KB smem ->
// 3 blocks/SM. Tiles of 128 edges interleaved between the two halves.
//   z1 = lrelu(u_i+u_j+be0); z2 = lrelu(z1@We1+be1) IN-PLACE; ep = z2@We2+be2;
//   write symmetric 4x4 blocks to X at (i,j) and (j,i).
// ---------------------------------------------------------------------------
#define K3_SMEM_FLOATS 18496
__global__ __launch_bounds__(256, 3) void edge_kernel(
    const int* __restrict__ ud,   /* int32 pairs (i,j) */
    const float* __restrict__ be0,
    const float* __restrict__ We1, const float* __restrict__ be1,
    const float* __restrict__ We2, const float* __restrict__ be2,
    float* __restrict__ Xout)
{
    extern __shared__ float sm[];
    float* ug   = sm;              // 40*65 = 2600 (pad 2608)
    float* Z0   = sm + 2608;       // 8192
    float* Wsm  = sm + 10800;      // 4096
    float* wsh  = sm + 14896;      // 640
    float* part = sm + 15536;      // 2560
    float* b0   = sm + 18096;      // 64
    float* b1   = sm + 18160;      // 64
    float* b2   = sm + 18224;      // 16
    int*   si   = (int*)(sm + 18240); // 128
    int*   sj   = (int*)(sm + 18368); // 128

    const int tid = threadIdx.x;
    const int e  = tid & 127, kh = tid >> 7;
    const int eg = tid & 31,  og = tid >> 5;
    const int g    = blockIdx.x >> 1;
    const int half = blockIdx.x & 1;
    ull acc[16];

    {   // group's u rows into shared, stride 65
        const float* usrc = g_u + (size_t)g*NN*64;
        for (int idx = tid; idx < NN*64; idx += 256){
            int n = idx >> 6, k = idx & 63;
            ug[n*65+k] = usrc[idx];
        }
    }
    for (int i2 = tid; i2 < 4096; i2 += 256) Wsm[i2] = We1[i2];
    for (int i2 = tid; i2 < 64; i2 += 256){ b0[i2] = be0[i2]; b1[i2] = be1[i2]; }
    for (int i2 = tid; i2 < 640; i2 += 256) wsh[i2] = We2[i2];
    if (tid < 10) b2[tid] = be2[tid];

    float* Xg = Xout + (size_t)g*X_PER_G;

    for (int tile = half; tile < 7; tile += 2){
        const int m0 = tile*128;
        const int ecnt = min(128, M_EDGES - m0);

        __syncthreads();   // prev scatter done reading si/sj; setup visible (1st iter)
        if (tid < 128){
            int2 p = make_int2(0,0);
            if (tid < ecnt) p = *reinterpret_cast<const int2*>(ud + 2*(m0+tid));
            si[tid] = p.x; sj[tid] = p.y;
        }
        __syncthreads();

        {   // z1 -> Z0
            const bool valid = e < ecnt;
            const int i = si[e], j = sj[e];
            const float* ui = ug + i*65;
            const float* uj = ug + j*65;
            for (int k = kh*32; k < kh*32+32; k++){
                float v = 0.f;
                if (valid) v = lrelu(ui[k] + uj[k] + b0[k]);
                Z0[k*128+e] = v;
            }
        }
        __syncthreads();
        gemm_main(Z0, Wsm, eg, og, acc);
        gemm_store_smem<true, true>(Z0, b1, eg, og, acc);   // in-place
        __syncthreads();
        layer10(Z0, wsh, part, e, kh);
        __syncthreads();

#pragma unroll
        for (int p = 0; p < 4; p++){
            int idx = tid + p*256;              // 0..1023
            int ee = idx >> 3, side = (idx >> 2) & 1, a = idx & 3;
            if (ee < ecnt){
                int i = si[ee], j = sj[ee];
                const float* p0 = part + ee*10;
                const float* p1 = part + 1280 + ee*10;
                int s0=c_smat[a*4], s1=c_smat[a*4+1], s2=c_smat[a*4+2], s3=c_smat[a*4+3];
                float4 v = make_float4(p0[s0]+p1[s0]+b2[s0], p0[s1]+p1[s1]+b2[s1],
                                       p0[s2]+p1[s2]+b2[s2], p0[s3]+p1[s3]+b2[s3]);
                int bi = side ? j : i;
                int bj = side ? i : j;
                *reinterpret_cast<float4*>(Xg + (bi*4+a)*160 + bj*4) = v;
            }
        }
    }
}

// ---------------------------------------------------------------------------
extern "C" void kernel_launch(void* const* d_in, const int* in_sizes, int n_in,
                              void* d_out, int out_size)
{
    const float* x  = (const float*)d_in[0];
    // d_in[1] edge_index (unused: complete graph), d_in[3] edge_map (unused)
    const int*   ud = (const int*)d_in[2];   // int32 (JAX default x64 disabled)
    const float* Wg0 = (const float*)d_in[4];  const float* bg0 = (const float*)d_in[5];
    const float* Wg1 = (const float*)d_in[6];  const float* bg1 = (const float*)d_in[7];
    const float* Wg2 = (const float*)d_in[8];  const float* bg2 = (const float*)d_in[9];
    const float* Wn0 = (const float*)d_in[10]; const float* bn0 = (const float*)d_in[11];
    const float* Wn1 = (const float*)d_in[12]; const float* bn1 = (const float*)d_in[13];
    const float* Wn2 = (const float*)d_in[14]; const float* bn2 = (const float*)d_in[15];
    const float* We0 = (const float*)d_in[16]; const float* be0 = (const float*)d_in[17];
    const float* We1 = (const float*)d_in[18]; const float* be1 = (const float*)d_in[19];
    const float* We2 = (const float*)d_in[20]; const float* be2 = (const float*)d_in[21];

    // Adaptive output layout: reference returns (h, X).
    float* hout;
    float* Xout;
    size_t osz = (size_t)out_size;
    if (osz >= (size_t)H_ELEMS + X_ELEMS){
        hout = (float*)d_out;
        Xout = (float*)d_out + H_ELEMS;
    } else if (osz >= X_ELEMS){
        cudaGetSymbolAddress((void**)&hout, g_h);
        Xout = (float*)d_out;
    } else {
        hout = (float*)d_out;
        cudaGetSymbolAddress((void**)&Xout, g_x);
    }

    cudaFuncSetAttribute(node_kernel, cudaFuncAttributeMaxDynamicSharedMemorySize,
                         K2_SMEM_FLOATS*4);
    cudaFuncSetAttribute(edge_kernel, cudaFuncAttributeMaxDynamicSharedMemorySize,
                         K3_SMEM_FLOATS*4);

    dummy_kernel<<<1, 32>>>();
    dummy_kernel<<<1, 32>>>();
    dummy_kernel<<<1, 32>>>();
    dummy_kernel<<<1, 32>>>();
    gcn_kernel<<<NG, 128>>>(x, Wg0, bg0, Wg1, bg1, Wg2, bg2, hout);
    node_kernel<<<NODES/128, 256, K2_SMEM_FLOATS*4>>>(hout, Wn0, bn0, Wn1, bn1,
                                                      Wn2, bn2, We0, Xout);
    edge_kernel<<<NG*2, 256, K3_SMEM_FLOATS*4>>>(ud, be0, We1, be1,
                                                 We2, be2, Xout);
}